// round 1
// baseline (speedup 1.0000x reference)
#include <cuda_runtime.h>
#include <cstdint>

// ---------------------------------------------------------------------------
// SLAYER SNN forward:
//   spikes = (threefry_uniform(key=42, [32,300,3072]) < inp)      (exact bits)
//   a1 = spikes @ W1^T          [9600,410]
//   s1 = (psp(a1) >= 10)        psp: u[t] = d*u[t-1] + x[t], d = exp(-0.1)f32
//   a2 = s1 @ W2^T              [9600,10]
//   out[b,j,t] = (psp(a2) >= 10)
// ---------------------------------------------------------------------------

#define BATCH 32
#define TBINS 300
#define FIN   3072
#define HID   410
#define NOUT  10
#define MROWS (BATCH * TBINS)          // 9600
#define NTOT  (MROWS * FIN)            // 29491200
#define HALFN (NTOT / 2)               // 14745600

#define DECAY 0.90483743f              // correctly-rounded fp32 exp(-0.1)
#define THETA 10.0f

// Scratch (static device allocations; no cudaMalloc allowed)
__device__ float g_spikes[NTOT];       // [9600, 3072]
__device__ float g_a1[MROWS * HID];    // [9600, 410]
__device__ float g_s1[MROWS * HID];    // [9600, 410]
__device__ float g_a2[MROWS * NOUT];   // [9600, 10]

// ---------------------------------------------------------------------------
// Kernel 1: threefry-2x32 spike generation (bit-exact vs jax.random.uniform)
// counts = iota(n); pair (i, i+n/2); out0 -> bits[i], out1 -> bits[i+n/2]
// key = (0, 42)
// ---------------------------------------------------------------------------
__device__ __forceinline__ uint32_t rotl32(uint32_t x, int r) {
    return (x << r) | (x >> (32 - r));
}

__global__ void __launch_bounds__(256) spikegen_kernel(const float* __restrict__ inp) {
    uint32_t i = blockIdx.x * 256u + threadIdx.x;
    if (i >= HALFN) return;

    const uint32_t k0 = 0u;
    const uint32_t k1 = 42u;
    const uint32_t k2 = 0x1BD11BDAu ^ k0 ^ k1;   // 0x1BD11BF0

    uint32_t x0 = i + k0;
    uint32_t x1 = (i + HALFN) + k1;

#define TF_RND(r) { x0 += x1; x1 = rotl32(x1, (r)) ^ x0; }
    TF_RND(13) TF_RND(15) TF_RND(26) TF_RND(6)
    x0 += k1; x1 += k2 + 1u;
    TF_RND(17) TF_RND(29) TF_RND(16) TF_RND(24)
    x0 += k2; x1 += k0 + 2u;
    TF_RND(13) TF_RND(15) TF_RND(26) TF_RND(6)
    x0 += k0; x1 += k1 + 3u;
    TF_RND(17) TF_RND(29) TF_RND(16) TF_RND(24)
    x0 += k1; x1 += k2 + 4u;
    TF_RND(13) TF_RND(15) TF_RND(26) TF_RND(6)
    x0 += k2; x1 += k0 + 5u;
#undef TF_RND

    // jax uniform [0,1): bitcast((bits >> 9) | 0x3F800000) - 1
    float u0 = __uint_as_float((x0 >> 9) | 0x3F800000u) - 1.0f;
    float u1 = __uint_as_float((x1 >> 9) | 0x3F800000u) - 1.0f;

    // flat index -> (b, t, f); prob = inp[b, f]
    uint32_t ia = i;
    uint32_t ib = i + HALFN;
    uint32_t ba = ia / (TBINS * FIN);
    uint32_t fa = ia % FIN;
    uint32_t bb = ib / (TBINS * FIN);
    uint32_t fb = ib % FIN;

    float pa = __ldg(&inp[ba * FIN + fa]);
    float pb = __ldg(&inp[bb * FIN + fb]);

    g_spikes[ia] = (u0 < pa) ? 1.0f : 0.0f;
    g_spikes[ib] = (u1 < pb) ? 1.0f : 0.0f;
}

// ---------------------------------------------------------------------------
// Kernel 2: GEMM1  a1[m,n] = sum_k spikes[m,k] * W1[n,k]
// M=9600, N=410, K=3072. fp32, smem-tiled 128x64, BK=16, 256 thr, 8x4/thread.
// ---------------------------------------------------------------------------
#define BM 128
#define BN 64
#define BK 16

__global__ void __launch_bounds__(256) gemm1_kernel(const float* __restrict__ W1) {
    __shared__ float As[BK][BM];
    __shared__ float Bs[BK][BN];

    const int m0 = blockIdx.x * BM;
    const int n0 = blockIdx.y * BN;
    const int tid = threadIdx.x;
    const int tx = tid & 15;       // n group (4 cols)
    const int ty = tid >> 4;       // m group (8 rows)

    const int lr = tid >> 2;              // 0..63 (row within half-tile)
    const int lc = (tid & 3) * 4;         // 0,4,8,12 (k within BK)

    float acc[8][4];
#pragma unroll
    for (int i = 0; i < 8; i++)
#pragma unroll
        for (int j = 0; j < 4; j++) acc[i][j] = 0.0f;

    for (int kk0 = 0; kk0 < FIN; kk0 += BK) {
        // --- load A tile (128 x 16), transposed into As[k][m] ---
        {
            float4 v0 = *(const float4*)&g_spikes[(m0 + lr) * FIN + kk0 + lc];
            float4 v1 = *(const float4*)&g_spikes[(m0 + lr + 64) * FIN + kk0 + lc];
            As[lc + 0][lr] = v0.x; As[lc + 1][lr] = v0.y;
            As[lc + 2][lr] = v0.z; As[lc + 3][lr] = v0.w;
            As[lc + 0][lr + 64] = v1.x; As[lc + 1][lr + 64] = v1.y;
            As[lc + 2][lr + 64] = v1.z; As[lc + 3][lr + 64] = v1.w;
        }
        // --- load B tile (64 x 16) from W1, guarded, into Bs[k][n] ---
        {
            float4 w = make_float4(0.f, 0.f, 0.f, 0.f);
            if (n0 + lr < HID)
                w = *(const float4*)&W1[(n0 + lr) * FIN + kk0 + lc];
            Bs[lc + 0][lr] = w.x; Bs[lc + 1][lr] = w.y;
            Bs[lc + 2][lr] = w.z; Bs[lc + 3][lr] = w.w;
        }
        __syncthreads();

#pragma unroll
        for (int kk = 0; kk < BK; kk++) {
            float a[8], b[4];
            *(float4*)&a[0] = *(const float4*)&As[kk][ty * 8];
            *(float4*)&a[4] = *(const float4*)&As[kk][ty * 8 + 4];
            *(float4*)&b[0] = *(const float4*)&Bs[kk][tx * 4];
#pragma unroll
            for (int i = 0; i < 8; i++)
#pragma unroll
                for (int j = 0; j < 4; j++)
                    acc[i][j] = fmaf(a[i], b[j], acc[i][j]);
        }
        __syncthreads();
    }

#pragma unroll
    for (int i = 0; i < 8; i++) {
        int m = m0 + ty * 8 + i;
#pragma unroll
        for (int j = 0; j < 4; j++) {
            int n = n0 + tx * 4 + j;
            if (n < HID) g_a1[m * HID + n] = acc[i][j];
        }
    }
}

// ---------------------------------------------------------------------------
// Kernel 3: PSP + threshold over layer 1. One thread per (b, o).
// ---------------------------------------------------------------------------
__global__ void psp1_kernel() {
    int tid = blockIdx.x * blockDim.x + threadIdx.x;
    if (tid >= BATCH * HID) return;
    int b = tid / HID;
    int o = tid % HID;
    const float* src = &g_a1[(size_t)b * TBINS * HID + o];
    float* dst = &g_s1[(size_t)b * TBINS * HID + o];
    float u = 0.0f;
#pragma unroll 4
    for (int t = 0; t < TBINS; t++) {
        u = fmaf(DECAY, u, src[t * HID]);
        dst[t * HID] = (u >= THETA) ? 1.0f : 0.0f;
    }
}

// ---------------------------------------------------------------------------
// Kernel 4: GEMM2  a2[m,j] = sum_k s1[m,k] * W2[j,k]. One warp per m-row.
// ---------------------------------------------------------------------------
__global__ void __launch_bounds__(256) gemm2_kernel(const float* __restrict__ W2) {
    __shared__ float W2s[NOUT * HID];   // 4100 floats
    for (int idx = threadIdx.x; idx < NOUT * HID; idx += 256)
        W2s[idx] = W2[idx];
    __syncthreads();

    int warp = threadIdx.x >> 5;
    int lane = threadIdx.x & 31;
    int m = blockIdx.x * 8 + warp;

    float p[NOUT];
#pragma unroll
    for (int j = 0; j < NOUT; j++) p[j] = 0.0f;

    for (int k = lane; k < HID; k += 32) {
        float s = g_s1[m * HID + k];
#pragma unroll
        for (int j = 0; j < NOUT; j++)
            p[j] = fmaf(s, W2s[j * HID + k], p[j]);
    }
#pragma unroll
    for (int j = 0; j < NOUT; j++)
#pragma unroll
        for (int off = 16; off > 0; off >>= 1)
            p[j] += __shfl_down_sync(0xffffffffu, p[j], off);

    if (lane == 0) {
#pragma unroll
        for (int j = 0; j < NOUT; j++)
            g_a2[m * NOUT + j] = p[j];
    }
}

// ---------------------------------------------------------------------------
// Kernel 5: PSP + threshold layer 2, write out[b, j, t].
// ---------------------------------------------------------------------------
__global__ void psp2_kernel(float* __restrict__ out) {
    int tid = blockIdx.x * blockDim.x + threadIdx.x;
    if (tid >= BATCH * NOUT) return;
    int b = tid / NOUT;
    int j = tid % NOUT;
    float u = 0.0f;
#pragma unroll 4
    for (int t = 0; t < TBINS; t++) {
        u = fmaf(DECAY, u, g_a2[(b * TBINS + t) * NOUT + j]);
        out[(b * NOUT + j) * TBINS + t] = (u >= THETA) ? 1.0f : 0.0f;
    }
}

// ---------------------------------------------------------------------------
extern "C" void kernel_launch(void* const* d_in, const int* in_sizes, int n_in,
                              void* d_out, int out_size) {
    const float* inp = (const float*)d_in[0];   // [32,3,32,32]
    const float* W1  = (const float*)d_in[1];   // [410,3072]
    const float* W2  = (const float*)d_in[2];   // [10,410]
    float* out = (float*)d_out;                 // [32,10,300]

    spikegen_kernel<<<(HALFN + 255) / 256, 256>>>(inp);

    dim3 g1(MROWS / BM, (HID + BN - 1) / BN);   // (75, 7)
    gemm1_kernel<<<g1, 256>>>(W1);

    psp1_kernel<<<(BATCH * HID + 255) / 256, 256>>>();

    gemm2_kernel<<<MROWS / 8, 256>>>(W2);

    psp2_kernel<<<2, 160>>>(out);
}

// round 4
// speedup vs baseline: 2.4009x; 2.4009x over previous
#include <cuda_runtime.h>
#include <cuda_bf16.h>
#include <cstdint>

// ===========================================================================
// SLAYER SNN forward. GEMM1 on tensor cores via mma.sync.m16n8k16 (bf16),
// exact 3-way bf16 split of W1, fp32 accumulation.
// (tcgen05 is unavailable: harness compiles PTX at target sm_103, not sm_103a.)
// ===========================================================================

#define BATCH 32
#define TBINS 300
#define FIN   3072
#define HID   410
#define NOUT  10
#define MROWS (BATCH * TBINS)          // 9600
#define NTOT  (MROWS * FIN)
#define HALFN (NTOT / 2)
#define NPAD  448                      // 7 tiles of 64

#define DECAY 0.90483743f
#define THETA 10.0f

// GEMM1 tiling
#define BM 256
#define BN 64
#define BK 64
#define KCH (FIN / BK)                 // 48 k-chunks
#define BROWS (3 * BN)                 // 192 B rows per stage (3 parts)
#define A_ST_BYTES (BM * 128)          // 32768
#define B_ST_BYTES (BROWS * 128)       // 24576
#define STAGE_BYTES (A_ST_BYTES + B_ST_BYTES)   // 57344
#define NSTAGES 2
#define DSMEM_BYTES (NSTAGES * STAGE_BYTES)     // 114688
#define NCHUNK (STAGE_BYTES / 16)      // 3584 16B chunks / stage
#define ACHUNK (A_ST_BYTES / 16)       // 2048

#define SWZ128(off) ((off) ^ (((off) >> 3) & 0x70))

// Scratch
__device__ __align__(16) __nv_bfloat16 g_spikes[NTOT];        // [9600,3072]
__device__ __align__(16) __nv_bfloat16 g_W1s[3 * NPAD * FIN]; // zero-padded rows
__device__ __align__(16) float         g_a1[MROWS * HID];
__device__ __align__(16) __nv_bfloat16 g_s1[MROWS * HID];
__device__ __align__(16) float         g_a2[MROWS * NOUT];

// ---------------------------------------------------------------------------
__device__ __forceinline__ uint32_t smem_u32(const void* p) {
    uint32_t a;
    asm("{ .reg .u64 t; cvta.to.shared.u64 t, %1; cvt.u32.u64 %0, t; }" : "=r"(a) : "l"(p));
    return a;
}
__device__ __forceinline__ void cp16(uint32_t sa, const void* g) {
    asm volatile("cp.async.cg.shared.global [%0], [%1], 16;" :: "r"(sa), "l"(g));
}
__device__ __forceinline__ void ldsm4(uint32_t* r, uint32_t addr) {
    asm volatile("ldmatrix.sync.aligned.m8n8.x4.shared.b16 {%0,%1,%2,%3}, [%4];"
                 : "=r"(r[0]), "=r"(r[1]), "=r"(r[2]), "=r"(r[3]) : "r"(addr));
}
__device__ __forceinline__ void mma16816(float* c, const uint32_t* a,
                                         uint32_t b0, uint32_t b1) {
    asm volatile(
        "mma.sync.aligned.m16n8k16.row.col.f32.bf16.bf16.f32 "
        "{%0,%1,%2,%3}, {%4,%5,%6,%7}, {%8,%9}, {%0,%1,%2,%3};"
        : "+f"(c[0]), "+f"(c[1]), "+f"(c[2]), "+f"(c[3])
        : "r"(a[0]), "r"(a[1]), "r"(a[2]), "r"(a[3]), "r"(b0), "r"(b1));
}

// ---------------------------------------------------------------------------
// Kernel 1: threefry-2x32 spike generation -> bf16 (bit-exact vs jax)
// ---------------------------------------------------------------------------
__device__ __forceinline__ uint32_t rotl32(uint32_t x, int r) {
    return (x << r) | (x >> (32 - r));
}

__global__ void __launch_bounds__(256) spikegen_kernel(const float* __restrict__ inp) {
    uint32_t i = blockIdx.x * 256u + threadIdx.x;
    if (i >= HALFN) return;

    const uint32_t k0 = 0u, k1 = 42u, k2 = 0x1BD11BDAu ^ k0 ^ k1;
    uint32_t x0 = i + k0;
    uint32_t x1 = (i + HALFN) + k1;

#define TF_RND(r) { x0 += x1; x1 = rotl32(x1, (r)) ^ x0; }
    TF_RND(13) TF_RND(15) TF_RND(26) TF_RND(6)
    x0 += k1; x1 += k2 + 1u;
    TF_RND(17) TF_RND(29) TF_RND(16) TF_RND(24)
    x0 += k2; x1 += k0 + 2u;
    TF_RND(13) TF_RND(15) TF_RND(26) TF_RND(6)
    x0 += k0; x1 += k1 + 3u;
    TF_RND(17) TF_RND(29) TF_RND(16) TF_RND(24)
    x0 += k1; x1 += k2 + 4u;
    TF_RND(13) TF_RND(15) TF_RND(26) TF_RND(6)
    x0 += k2; x1 += k0 + 5u;
#undef TF_RND

    float u0 = __uint_as_float((x0 >> 9) | 0x3F800000u) - 1.0f;
    float u1 = __uint_as_float((x1 >> 9) | 0x3F800000u) - 1.0f;

    uint32_t ia = i, ib = i + HALFN;
    uint32_t ba = ia / (TBINS * FIN), fa = ia % FIN;
    uint32_t bb = ib / (TBINS * FIN), fb = ib % FIN;
    float pa = __ldg(&inp[ba * FIN + fa]);
    float pb = __ldg(&inp[bb * FIN + fb]);

    g_spikes[ia] = __float2bfloat16((u0 < pa) ? 1.0f : 0.0f);
    g_spikes[ib] = __float2bfloat16((u1 < pb) ? 1.0f : 0.0f);
}

// ---------------------------------------------------------------------------
// Kernel 2: exact 3-way bf16 split of W1 into g_W1s[part][NPAD][3072]
// ---------------------------------------------------------------------------
__global__ void __launch_bounds__(256) wsplit_kernel(const float* __restrict__ W1) {
    int i = blockIdx.x * 256 + threadIdx.x;
    if (i >= HID * FIN) return;
    float w = W1[i];
    __nv_bfloat16 h = __float2bfloat16(w);
    float r1 = w - __bfloat162float(h);
    __nv_bfloat16 m = __float2bfloat16(r1);
    float r2 = r1 - __bfloat162float(m);
    __nv_bfloat16 l = __float2bfloat16(r2);
    int n = i / FIN, k = i % FIN;
    g_W1s[(0 * NPAD + n) * FIN + k] = h;
    g_W1s[(1 * NPAD + n) * FIN + k] = m;
    g_W1s[(2 * NPAD + n) * FIN + k] = l;
}

// ---------------------------------------------------------------------------
// Kernel 3: GEMM1, mma.sync bf16, 2-stage cp.async pipeline, SW128 smem.
// ---------------------------------------------------------------------------
__device__ __forceinline__ void load_stage(uint32_t sbase, int m0, int n0, int k0,
                                           int tid) {
    uint32_t stB = sbase + A_ST_BYTES;
#pragma unroll
    for (int c = tid; c < NCHUNK; c += 256) {
        uint32_t sa;
        const __nv_bfloat16* g;
        if (c < ACHUNK) {
            int row = c >> 3, q = c & 7;
            int m = m0 + row;
            if (m >= MROWS) m = MROWS - 1;                  // clamp (discarded later)
            sa = sbase + SWZ128(row * 128 + q * 16);
            g = &g_spikes[(size_t)m * FIN + k0 + q * 8];
        } else {
            int cc = c - ACHUNK;
            int br = cc >> 3, q = cc & 7;
            int part = br >> 6, nr = br & 63;
            sa = stB + SWZ128(br * 128 + q * 16);
            g = &g_W1s[((size_t)part * NPAD + n0 + nr) * FIN + k0 + q * 8];
        }
        cp16(sa, g);
    }
    asm volatile("cp.async.commit_group;" ::: "memory");
}

__global__ void __launch_bounds__(256, 2) gemm1_mma_kernel() {
    extern __shared__ char dsmem[];
    const int tid = threadIdx.x;
    const int lane = tid & 31, wid = tid >> 5;
    const int wm = wid & 3;          // warp m index (4)
    const int wn = wid >> 2;         // warp n index (2)
    const int m0 = blockIdx.x * BM;
    const int n0 = blockIdx.y * BN;

    const uint32_t sbase = smem_u32(dsmem);

    float acc[4][4][4];
#pragma unroll
    for (int i = 0; i < 4; i++)
#pragma unroll
        for (int j = 0; j < 4; j++)
#pragma unroll
            for (int c = 0; c < 4; c++) acc[i][j][c] = 0.0f;

    // ldmatrix lane addressing pieces
    const int ltr = (lane & 7) + ((lane >> 3) & 1) * 8;   // row within 16
    const int lkb = (lane >> 4) * 16;                     // 0 or 16 (k-byte half)

    load_stage(sbase, m0, n0, 0, tid);

    for (int kc = 0; kc < KCH; kc++) {
        if (kc + 1 < KCH) {
            load_stage(sbase + ((kc + 1) & 1) * STAGE_BYTES, m0, n0, (kc + 1) * BK, tid);
            asm volatile("cp.async.wait_group 1;" ::: "memory");
        } else {
            asm volatile("cp.async.wait_group 0;" ::: "memory");
        }
        __syncthreads();

        const uint32_t sA = sbase + (kc & 1) * STAGE_BYTES;
        const uint32_t sB = sA + A_ST_BYTES;

#pragma unroll
        for (int kt = 0; kt < 4; kt++) {
            const int kb = kt * 32 + lkb;
            uint32_t aF[4][4];
#pragma unroll
            for (int im = 0; im < 4; im++) {
                int row = wm * 64 + im * 16 + ltr;
                ldsm4(aF[im], sA + SWZ128(row * 128 + kb));
            }
#pragma unroll
            for (int part = 0; part < 3; part++) {
                uint32_t bF[2][4];
#pragma unroll
                for (int j = 0; j < 2; j++) {
                    int row = part * 64 + wn * 32 + j * 16 + ltr;
                    ldsm4(bF[j], sB + SWZ128(row * 128 + kb));
                }
#pragma unroll
                for (int im = 0; im < 4; im++) {
#pragma unroll
                    for (int j = 0; j < 2; j++) {
                        mma16816(acc[im][j * 2 + 0], aF[im], bF[j][0], bF[j][2]);
                        mma16816(acc[im][j * 2 + 1], aF[im], bF[j][1], bF[j][3]);
                    }
                }
            }
        }
        __syncthreads();
    }

    // epilogue: c0,c1 -> (m = g, n, n+1); c2,c3 -> (m = g+8)
#pragma unroll
    for (int im = 0; im < 4; im++) {
        int m = m0 + wm * 64 + im * 16 + (lane >> 2);
#pragma unroll
        for (int jn = 0; jn < 4; jn++) {
            int n = n0 + wn * 32 + jn * 8 + (lane & 3) * 2;
            if (n < HID) {   // n,HID even -> n+1 < HID too
                if (m < MROWS)
                    *(float2*)&g_a1[(size_t)m * HID + n] =
                        make_float2(acc[im][jn][0], acc[im][jn][1]);
                if (m + 8 < MROWS)
                    *(float2*)&g_a1[(size_t)(m + 8) * HID + n] =
                        make_float2(acc[im][jn][2], acc[im][jn][3]);
            }
        }
    }
}

// ---------------------------------------------------------------------------
// Kernel 4: PSP + threshold layer 1 -> bf16 spikes
// ---------------------------------------------------------------------------
__global__ void psp1_kernel() {
    int tid = blockIdx.x * blockDim.x + threadIdx.x;
    if (tid >= BATCH * HID) return;
    int b = tid / HID;
    int o = tid % HID;
    const float* src = &g_a1[(size_t)b * TBINS * HID + o];
    __nv_bfloat16* dst = &g_s1[(size_t)b * TBINS * HID + o];
    float u = 0.0f;
#pragma unroll 10
    for (int t = 0; t < TBINS; t++) {
        u = fmaf(DECAY, u, src[t * HID]);
        dst[t * HID] = __float2bfloat16((u >= THETA) ? 1.0f : 0.0f);
    }
}

// ---------------------------------------------------------------------------
// Kernel 5: GEMM2 (one warp per row)
// ---------------------------------------------------------------------------
__global__ void __launch_bounds__(256) gemm2_kernel(const float* __restrict__ W2) {
    __shared__ float W2s[NOUT * HID];
    for (int idx = threadIdx.x; idx < NOUT * HID; idx += 256)
        W2s[idx] = W2[idx];
    __syncthreads();

    int warp = threadIdx.x >> 5;
    int lane = threadIdx.x & 31;
    int m = blockIdx.x * 8 + warp;

    float p[NOUT];
#pragma unroll
    for (int j = 0; j < NOUT; j++) p[j] = 0.0f;

    for (int k = lane; k < HID; k += 32) {
        float s = __bfloat162float(g_s1[m * HID + k]);
#pragma unroll
        for (int j = 0; j < NOUT; j++)
            p[j] = fmaf(s, W2s[j * HID + k], p[j]);
    }
#pragma unroll
    for (int j = 0; j < NOUT; j++)
#pragma unroll
        for (int off = 16; off > 0; off >>= 1)
            p[j] += __shfl_down_sync(0xffffffffu, p[j], off);

    if (lane == 0) {
#pragma unroll
        for (int j = 0; j < NOUT; j++)
            g_a2[m * NOUT + j] = p[j];
    }
}

// ---------------------------------------------------------------------------
// Kernel 6: PSP + threshold layer 2 -> out[b, j, t]
// ---------------------------------------------------------------------------
__global__ void psp2_kernel(float* __restrict__ out) {
    int tid = blockIdx.x * blockDim.x + threadIdx.x;
    if (tid >= BATCH * NOUT) return;
    int b = tid / NOUT;
    int j = tid % NOUT;
    float u = 0.0f;
#pragma unroll 10
    for (int t = 0; t < TBINS; t++) {
        u = fmaf(DECAY, u, g_a2[(b * TBINS + t) * NOUT + j]);
        out[(b * NOUT + j) * TBINS + t] = (u >= THETA) ? 1.0f : 0.0f;
    }
}

// ---------------------------------------------------------------------------
extern "C" void kernel_launch(void* const* d_in, const int* in_sizes, int n_in,
                              void* d_out, int out_size) {
    const float* inp = (const float*)d_in[0];   // [32,3,32,32]
    const float* W1  = (const float*)d_in[1];   // [410,3072]
    const float* W2  = (const float*)d_in[2];   // [10,410]
    float* out = (float*)d_out;                 // [32,10,300]

    cudaFuncSetAttribute(gemm1_mma_kernel,
                         cudaFuncAttributeMaxDynamicSharedMemorySize, DSMEM_BYTES);

    spikegen_kernel<<<(HALFN + 255) / 256, 256>>>(inp);
    wsplit_kernel<<<(HID * FIN + 255) / 256, 256>>>(W1);

    dim3 g1((MROWS + BM - 1) / BM, NPAD / BN);   // (38, 7)
    gemm1_mma_kernel<<<g1, 256, DSMEM_BYTES>>>();

    psp1_kernel<<<(BATCH * HID + 255) / 256, 256>>>();
    gemm2_kernel<<<MROWS / 8, 256>>>(W2);
    psp2_kernel<<<2, 160>>>(out);
}

// round 5
// speedup vs baseline: 2.8722x; 1.1963x over previous
#include <cuda_runtime.h>
#include <cuda_bf16.h>
#include <cstdint>

// ===========================================================================
// SLAYER SNN forward. GEMM1 on tensor cores via mma.sync.m16n8k16 (bf16),
// exact 3-way bf16 split of W1, fp32 accumulation. PSP kernels use deep
// load-batching to break the latency chain.
// ===========================================================================

#define BATCH 32
#define TBINS 300
#define FIN   3072
#define HID   410
#define NOUT  10
#define MROWS (BATCH * TBINS)          // 9600
#define NTOT  (MROWS * FIN)
#define HALFN (NTOT / 2)
#define NPAD  448                      // 7 tiles of 64

#define DECAY 0.90483743f
#define THETA 10.0f

// GEMM1 tiling
#define BM 256
#define BN 64
#define BK 64
#define KCH (FIN / BK)                 // 48 k-chunks
#define BROWS (3 * BN)                 // 192 B rows per stage (3 parts)
#define A_ST_BYTES (BM * 128)          // 32768
#define B_ST_BYTES (BROWS * 128)       // 24576
#define STAGE_BYTES (A_ST_BYTES + B_ST_BYTES)   // 57344
#define NSTAGES 2
#define DSMEM_BYTES (NSTAGES * STAGE_BYTES)     // 114688
#define NCHUNK (STAGE_BYTES / 16)      // 3584 16B chunks / stage
#define ACHUNK (A_ST_BYTES / 16)       // 2048

#define SWZ128(off) ((off) ^ (((off) >> 3) & 0x70))

// Scratch
__device__ __align__(16) __nv_bfloat16 g_spikes[NTOT];        // [9600,3072]
__device__ __align__(16) __nv_bfloat16 g_W1s[3 * NPAD * FIN]; // zero-padded rows
__device__ __align__(16) float         g_a1[MROWS * HID];
__device__ __align__(16) __nv_bfloat16 g_s1[MROWS * HID];
__device__ __align__(16) float         g_a2[MROWS * NOUT];

// ---------------------------------------------------------------------------
__device__ __forceinline__ uint32_t smem_u32(const void* p) {
    uint32_t a;
    asm("{ .reg .u64 t; cvta.to.shared.u64 t, %1; cvt.u32.u64 %0, t; }" : "=r"(a) : "l"(p));
    return a;
}
__device__ __forceinline__ void cp16(uint32_t sa, const void* g) {
    asm volatile("cp.async.cg.shared.global [%0], [%1], 16;" :: "r"(sa), "l"(g));
}
__device__ __forceinline__ void ldsm4(uint32_t* r, uint32_t addr) {
    asm volatile("ldmatrix.sync.aligned.m8n8.x4.shared.b16 {%0,%1,%2,%3}, [%4];"
                 : "=r"(r[0]), "=r"(r[1]), "=r"(r[2]), "=r"(r[3]) : "r"(addr));
}
__device__ __forceinline__ void mma16816(float* c, const uint32_t* a,
                                         uint32_t b0, uint32_t b1) {
    asm volatile(
        "mma.sync.aligned.m16n8k16.row.col.f32.bf16.bf16.f32 "
        "{%0,%1,%2,%3}, {%4,%5,%6,%7}, {%8,%9}, {%0,%1,%2,%3};"
        : "+f"(c[0]), "+f"(c[1]), "+f"(c[2]), "+f"(c[3])
        : "r"(a[0]), "r"(a[1]), "r"(a[2]), "r"(a[3]), "r"(b0), "r"(b1));
}

// ---------------------------------------------------------------------------
// Kernel 1: threefry-2x32 spike generation -> bf16 (bit-exact vs jax).
// Also performs the exact 3-way bf16 split of W1 on its first HID*FIN threads.
// ---------------------------------------------------------------------------
__device__ __forceinline__ uint32_t rotl32(uint32_t x, int r) {
    return (x << r) | (x >> (32 - r));
}

__global__ void __launch_bounds__(256) spikegen_kernel(const float* __restrict__ inp,
                                                       const float* __restrict__ W1) {
    uint32_t i = blockIdx.x * 256u + threadIdx.x;
    if (i >= HALFN) return;

    // --- W1 split (piggybacked on first 1.26M threads) ---
    if (i < HID * FIN) {
        float w = W1[i];
        __nv_bfloat16 h = __float2bfloat16(w);
        float r1 = w - __bfloat162float(h);
        __nv_bfloat16 m = __float2bfloat16(r1);
        float r2 = r1 - __bfloat162float(m);
        __nv_bfloat16 l = __float2bfloat16(r2);
        int n = i / FIN, k = i % FIN;
        g_W1s[(0 * NPAD + n) * FIN + k] = h;
        g_W1s[(1 * NPAD + n) * FIN + k] = m;
        g_W1s[(2 * NPAD + n) * FIN + k] = l;
    }

    const uint32_t k0 = 0u, k1 = 42u, k2 = 0x1BD11BDAu ^ k0 ^ k1;
    uint32_t x0 = i + k0;
    uint32_t x1 = (i + HALFN) + k1;

#define TF_RND(r) { x0 += x1; x1 = rotl32(x1, (r)) ^ x0; }
    TF_RND(13) TF_RND(15) TF_RND(26) TF_RND(6)
    x0 += k1; x1 += k2 + 1u;
    TF_RND(17) TF_RND(29) TF_RND(16) TF_RND(24)
    x0 += k2; x1 += k0 + 2u;
    TF_RND(13) TF_RND(15) TF_RND(26) TF_RND(6)
    x0 += k0; x1 += k1 + 3u;
    TF_RND(17) TF_RND(29) TF_RND(16) TF_RND(24)
    x0 += k1; x1 += k2 + 4u;
    TF_RND(13) TF_RND(15) TF_RND(26) TF_RND(6)
    x0 += k2; x1 += k0 + 5u;
#undef TF_RND

    float u0 = __uint_as_float((x0 >> 9) | 0x3F800000u) - 1.0f;
    float u1 = __uint_as_float((x1 >> 9) | 0x3F800000u) - 1.0f;

    uint32_t ia = i, ib = i + HALFN;
    uint32_t ba = ia / (TBINS * FIN), fa = ia % FIN;
    uint32_t bb = ib / (TBINS * FIN), fb = ib % FIN;
    float pa = __ldg(&inp[ba * FIN + fa]);
    float pb = __ldg(&inp[bb * FIN + fb]);

    g_spikes[ia] = __float2bfloat16((u0 < pa) ? 1.0f : 0.0f);
    g_spikes[ib] = __float2bfloat16((u1 < pb) ? 1.0f : 0.0f);
}

// ---------------------------------------------------------------------------
// Kernel 2: GEMM1, mma.sync bf16, 2-stage cp.async pipeline, SW128 smem.
// ---------------------------------------------------------------------------
__device__ __forceinline__ void load_stage(uint32_t sbase, int m0, int n0, int k0,
                                           int tid) {
    uint32_t stB = sbase + A_ST_BYTES;
#pragma unroll
    for (int c = tid; c < NCHUNK; c += 256) {
        uint32_t sa;
        const __nv_bfloat16* g;
        if (c < ACHUNK) {
            int row = c >> 3, q = c & 7;
            int m = m0 + row;
            if (m >= MROWS) m = MROWS - 1;                  // clamp (discarded later)
            sa = sbase + SWZ128(row * 128 + q * 16);
            g = &g_spikes[(size_t)m * FIN + k0 + q * 8];
        } else {
            int cc = c - ACHUNK;
            int br = cc >> 3, q = cc & 7;
            int part = br >> 6, nr = br & 63;
            sa = stB + SWZ128(br * 128 + q * 16);
            g = &g_W1s[((size_t)part * NPAD + n0 + nr) * FIN + k0 + q * 8];
        }
        cp16(sa, g);
    }
    asm volatile("cp.async.commit_group;" ::: "memory");
}

__global__ void __launch_bounds__(256, 2) gemm1_mma_kernel() {
    extern __shared__ char dsmem[];
    const int tid = threadIdx.x;
    const int lane = tid & 31, wid = tid >> 5;
    const int wm = wid & 3;          // warp m index (4)
    const int wn = wid >> 2;         // warp n index (2)
    const int m0 = blockIdx.x * BM;
    const int n0 = blockIdx.y * BN;

    const uint32_t sbase = smem_u32(dsmem);

    float acc[4][4][4];
#pragma unroll
    for (int i = 0; i < 4; i++)
#pragma unroll
        for (int j = 0; j < 4; j++)
#pragma unroll
            for (int c = 0; c < 4; c++) acc[i][j][c] = 0.0f;

    const int ltr = (lane & 7) + ((lane >> 3) & 1) * 8;   // row within 16
    const int lkb = (lane >> 4) * 16;                     // 0 or 16 (k-byte half)

    load_stage(sbase, m0, n0, 0, tid);

    for (int kc = 0; kc < KCH; kc++) {
        if (kc + 1 < KCH) {
            load_stage(sbase + ((kc + 1) & 1) * STAGE_BYTES, m0, n0, (kc + 1) * BK, tid);
            asm volatile("cp.async.wait_group 1;" ::: "memory");
        } else {
            asm volatile("cp.async.wait_group 0;" ::: "memory");
        }
        __syncthreads();

        const uint32_t sA = sbase + (kc & 1) * STAGE_BYTES;
        const uint32_t sB = sA + A_ST_BYTES;

#pragma unroll
        for (int kt = 0; kt < 4; kt++) {
            const int kb = kt * 32 + lkb;
            uint32_t aF[4][4];
#pragma unroll
            for (int im = 0; im < 4; im++) {
                int row = wm * 64 + im * 16 + ltr;
                ldsm4(aF[im], sA + SWZ128(row * 128 + kb));
            }
#pragma unroll
            for (int part = 0; part < 3; part++) {
                uint32_t bF[2][4];
#pragma unroll
                for (int j = 0; j < 2; j++) {
                    int row = part * 64 + wn * 32 + j * 16 + ltr;
                    ldsm4(bF[j], sB + SWZ128(row * 128 + kb));
                }
#pragma unroll
                for (int im = 0; im < 4; im++) {
#pragma unroll
                    for (int j = 0; j < 2; j++) {
                        mma16816(acc[im][j * 2 + 0], aF[im], bF[j][0], bF[j][2]);
                        mma16816(acc[im][j * 2 + 1], aF[im], bF[j][1], bF[j][3]);
                    }
                }
            }
        }
        __syncthreads();
    }

#pragma unroll
    for (int im = 0; im < 4; im++) {
        int m = m0 + wm * 64 + im * 16 + (lane >> 2);
#pragma unroll
        for (int jn = 0; jn < 4; jn++) {
            int n = n0 + wn * 32 + jn * 8 + (lane & 3) * 2;
            if (n < HID) {
                if (m < MROWS)
                    *(float2*)&g_a1[(size_t)m * HID + n] =
                        make_float2(acc[im][jn][0], acc[im][jn][1]);
                if (m + 8 < MROWS)
                    *(float2*)&g_a1[(size_t)(m + 8) * HID + n] =
                        make_float2(acc[im][jn][2], acc[im][jn][3]);
            }
        }
    }
}

// ---------------------------------------------------------------------------
// Kernel 3: PSP + threshold layer 1 -> bf16. Batch-10 load prefetch (MLP=10).
// ---------------------------------------------------------------------------
__global__ void __launch_bounds__(256) psp1_kernel() {
    int tid = blockIdx.x * blockDim.x + threadIdx.x;
    if (tid >= BATCH * HID) return;
    int b = tid / HID;
    int o = tid % HID;
    const float* src = &g_a1[(size_t)b * TBINS * HID + o];
    __nv_bfloat16* dst = &g_s1[(size_t)b * TBINS * HID + o];
    float u = 0.0f;
    for (int tb = 0; tb < TBINS; tb += 10) {
        float x[10];
#pragma unroll
        for (int q = 0; q < 10; q++) x[q] = src[(tb + q) * HID];
#pragma unroll
        for (int q = 0; q < 10; q++) {
            u = fmaf(DECAY, u, x[q]);
            dst[(tb + q) * HID] = __float2bfloat16((u >= THETA) ? 1.0f : 0.0f);
        }
    }
}

// ---------------------------------------------------------------------------
// Kernel 4: GEMM2 (one warp per row, bf16x2 vectorized)
// ---------------------------------------------------------------------------
__global__ void __launch_bounds__(256) gemm2_kernel(const float* __restrict__ W2) {
    __shared__ float2 W2s[NOUT][(HID + 1) / 2 + 1];   // paired (k, k+1); pad k=410 with 0
    for (int idx = threadIdx.x; idx < NOUT * 206; idx += 256) {
        int j = idx / 206, kp = idx % 206;
        float w0 = (kp * 2 < HID) ? W2[j * HID + kp * 2] : 0.0f;
        float w1 = (kp * 2 + 1 < HID) ? W2[j * HID + kp * 2 + 1] : 0.0f;
        W2s[j][kp] = make_float2(w0, w1);
    }
    __syncthreads();

    int warp = threadIdx.x >> 5;
    int lane = threadIdx.x & 31;
    int m = blockIdx.x * 8 + warp;

    float p[NOUT];
#pragma unroll
    for (int j = 0; j < NOUT; j++) p[j] = 0.0f;

    // 205 bf16 pairs; lane kp covers kp, kp+32, ... (7 iters; last partial)
    for (int kp = lane; kp < 205; kp += 32) {
        __nv_bfloat162 sv = *(const __nv_bfloat162*)&g_s1[m * HID + kp * 2];
        float s0 = __bfloat162float(sv.x);
        float s1v = __bfloat162float(sv.y);
#pragma unroll
        for (int j = 0; j < NOUT; j++) {
            float2 w = W2s[j][kp];
            p[j] = fmaf(s0, w.x, fmaf(s1v, w.y, p[j]));
        }
    }
    // k = 410-1 = last even index 410? HID=410 -> pairs 0..204 cover k 0..409. done.

#pragma unroll
    for (int j = 0; j < NOUT; j++)
#pragma unroll
        for (int off = 16; off > 0; off >>= 1)
            p[j] += __shfl_down_sync(0xffffffffu, p[j], off);

    if (lane == 0) {
#pragma unroll
        for (int j = 0; j < NOUT; j++)
            g_a2[m * NOUT + j] = p[j];
    }
}

// ---------------------------------------------------------------------------
// Kernel 5: PSP + threshold layer 2 -> out[b, j, t]. Batch-10 prefetch.
// ---------------------------------------------------------------------------
__global__ void psp2_kernel(float* __restrict__ out) {
    int tid = blockIdx.x * blockDim.x + threadIdx.x;
    if (tid >= BATCH * NOUT) return;
    int b = tid / NOUT;
    int j = tid % NOUT;
    const float* src = &g_a2[(size_t)b * TBINS * NOUT + j];
    float* dst = &out[((size_t)b * NOUT + j) * TBINS];
    float u = 0.0f;
    for (int tb = 0; tb < TBINS; tb += 10) {
        float x[10];
#pragma unroll
        for (int q = 0; q < 10; q++) x[q] = src[(tb + q) * NOUT];
#pragma unroll
        for (int q = 0; q < 10; q++) {
            u = fmaf(DECAY, u, x[q]);
            dst[tb + q] = (u >= THETA) ? 1.0f : 0.0f;
        }
    }
}

// ---------------------------------------------------------------------------
extern "C" void kernel_launch(void* const* d_in, const int* in_sizes, int n_in,
                              void* d_out, int out_size) {
    const float* inp = (const float*)d_in[0];   // [32,3,32,32]
    const float* W1  = (const float*)d_in[1];   // [410,3072]
    const float* W2  = (const float*)d_in[2];   // [10,410]
    float* out = (float*)d_out;                 // [32,10,300]

    cudaFuncSetAttribute(gemm1_mma_kernel,
                         cudaFuncAttributeMaxDynamicSharedMemorySize, DSMEM_BYTES);

    spikegen_kernel<<<(HALFN + 255) / 256, 256>>>(inp, W1);

    dim3 g1((MROWS + BM - 1) / BM, NPAD / BN);   // (38, 7)
    gemm1_mma_kernel<<<g1, 256, DSMEM_BYTES>>>();

    psp1_kernel<<<(BATCH * HID + 255) / 256, 256>>>();
    gemm2_kernel<<<MROWS / 8, 256>>>(W2);
    psp2_kernel<<<2, 160>>>(out);
}

// round 6
// speedup vs baseline: 3.5081x; 1.2214x over previous
#include <cuda_runtime.h>
#include <cuda_fp16.h>
#include <cuda_bf16.h>
#include <cstdint>

// ===========================================================================
// SLAYER SNN forward. GEMM1 on tensor cores via mma.sync.m16n8k16 (fp16),
// exact-to-~3e-8 2-part fp16 split of W1 (hi + mid), fp32 accumulation.
// ===========================================================================

#define BATCH 32
#define TBINS 300
#define FIN   3072
#define HID   410
#define NOUT  10
#define MROWS (BATCH * TBINS)          // 9600
#define NTOT  (MROWS * FIN)
#define HALFN (NTOT / 2)
#define NPAD  448                      // 7 tiles of 64

#define DECAY 0.90483743f
#define THETA 10.0f

// GEMM1 tiling
#define NPARTS 2
#define BM 256
#define BN 64
#define BK 64
#define KCH (FIN / BK)                 // 48 k-chunks
#define BROWS (NPARTS * BN)            // 128 B rows per stage
#define A_ST_BYTES (BM * 128)          // 32768
#define B_ST_BYTES (BROWS * 128)       // 16384
#define STAGE_BYTES (A_ST_BYTES + B_ST_BYTES)   // 49152
#define NSTAGES 2
#define DSMEM_BYTES (NSTAGES * STAGE_BYTES)     // 98304
#define NCHUNK (STAGE_BYTES / 16)      // 3072 16B chunks / stage
#define ACHUNK (A_ST_BYTES / 16)       // 2048

#define SWZ128(off) ((off) ^ (((off) >> 3) & 0x70))

// Scratch
__device__ __align__(16) __half        g_spikes[NTOT];        // [9600,3072] 0/1
__device__ __align__(16) __half        g_W1s[NPARTS * NPAD * FIN]; // zero-padded rows
__device__ __align__(16) float         g_a1[MROWS * HID];
__device__ __align__(16) __nv_bfloat16 g_s1[MROWS * HID];
__device__ __align__(16) float         g_a2[MROWS * NOUT];

// ---------------------------------------------------------------------------
__device__ __forceinline__ uint32_t smem_u32(const void* p) {
    uint32_t a;
    asm("{ .reg .u64 t; cvta.to.shared.u64 t, %1; cvt.u32.u64 %0, t; }" : "=r"(a) : "l"(p));
    return a;
}
__device__ __forceinline__ void cp16(uint32_t sa, const void* g) {
    asm volatile("cp.async.cg.shared.global [%0], [%1], 16;" :: "r"(sa), "l"(g));
}
__device__ __forceinline__ void ldsm4(uint32_t* r, uint32_t addr) {
    asm volatile("ldmatrix.sync.aligned.m8n8.x4.shared.b16 {%0,%1,%2,%3}, [%4];"
                 : "=r"(r[0]), "=r"(r[1]), "=r"(r[2]), "=r"(r[3]) : "r"(addr));
}
__device__ __forceinline__ void mma16816(float* c, const uint32_t* a,
                                         uint32_t b0, uint32_t b1) {
    asm volatile(
        "mma.sync.aligned.m16n8k16.row.col.f32.f16.f16.f32 "
        "{%0,%1,%2,%3}, {%4,%5,%6,%7}, {%8,%9}, {%0,%1,%2,%3};"
        : "+f"(c[0]), "+f"(c[1]), "+f"(c[2]), "+f"(c[3])
        : "r"(a[0]), "r"(a[1]), "r"(a[2]), "r"(a[3]), "r"(b0), "r"(b1));
}

// ---------------------------------------------------------------------------
// Kernel 1: threefry-2x32 spike generation -> fp16 (bit-exact vs jax).
// Also performs the 2-part fp16 split of W1 on its first HID*FIN threads.
// ---------------------------------------------------------------------------
__device__ __forceinline__ uint32_t rotl32(uint32_t x, int r) {
    return (x << r) | (x >> (32 - r));
}

__global__ void __launch_bounds__(256) spikegen_kernel(const float* __restrict__ inp,
                                                       const float* __restrict__ W1) {
    uint32_t i = blockIdx.x * 256u + threadIdx.x;
    if (i >= HALFN) return;

    // --- W1 split (piggybacked on first 1.26M threads) ---
    if (i < HID * FIN) {
        float w = W1[i];
        __half h = __float2half_rn(w);
        float r1 = w - __half2float(h);
        __half m = __float2half_rn(r1);
        int n = i / FIN, k = i % FIN;
        g_W1s[(0 * NPAD + n) * FIN + k] = h;
        g_W1s[(1 * NPAD + n) * FIN + k] = m;
    }

    const uint32_t k0 = 0u, k1 = 42u, k2 = 0x1BD11BDAu ^ k0 ^ k1;
    uint32_t x0 = i + k0;
    uint32_t x1 = (i + HALFN) + k1;

#define TF_RND(r) { x0 += x1; x1 = rotl32(x1, (r)) ^ x0; }
    TF_RND(13) TF_RND(15) TF_RND(26) TF_RND(6)
    x0 += k1; x1 += k2 + 1u;
    TF_RND(17) TF_RND(29) TF_RND(16) TF_RND(24)
    x0 += k2; x1 += k0 + 2u;
    TF_RND(13) TF_RND(15) TF_RND(26) TF_RND(6)
    x0 += k0; x1 += k1 + 3u;
    TF_RND(17) TF_RND(29) TF_RND(16) TF_RND(24)
    x0 += k1; x1 += k2 + 4u;
    TF_RND(13) TF_RND(15) TF_RND(26) TF_RND(6)
    x0 += k2; x1 += k0 + 5u;
#undef TF_RND

    float u0 = __uint_as_float((x0 >> 9) | 0x3F800000u) - 1.0f;
    float u1 = __uint_as_float((x1 >> 9) | 0x3F800000u) - 1.0f;

    uint32_t ia = i, ib = i + HALFN;
    uint32_t ba = ia / (TBINS * FIN), fa = ia % FIN;
    uint32_t bb = ib / (TBINS * FIN), fb = ib % FIN;
    float pa = __ldg(&inp[ba * FIN + fa]);
    float pb = __ldg(&inp[bb * FIN + fb]);

    g_spikes[ia] = __ushort_as_half((u0 < pa) ? (unsigned short)0x3C00 : (unsigned short)0);
    g_spikes[ib] = __ushort_as_half((u1 < pb) ? (unsigned short)0x3C00 : (unsigned short)0);
}

// ---------------------------------------------------------------------------
// Kernel 2: GEMM1, mma.sync fp16, 2-stage cp.async pipeline, SW128 smem.
// a1[m,n] = sum_k spikes[m,k] * (W1hi + W1mid)[n,k]
// ---------------------------------------------------------------------------
__device__ __forceinline__ void load_stage(uint32_t sbase, int m0, int n0, int k0,
                                           int tid) {
    uint32_t stB = sbase + A_ST_BYTES;
#pragma unroll
    for (int c = tid; c < NCHUNK; c += 256) {
        uint32_t sa;
        const __half* g;
        if (c < ACHUNK) {
            int row = c >> 3, q = c & 7;
            int m = m0 + row;
            if (m >= MROWS) m = MROWS - 1;                  // clamp (discarded later)
            sa = sbase + SWZ128(row * 128 + q * 16);
            g = &g_spikes[(size_t)m * FIN + k0 + q * 8];
        } else {
            int cc = c - ACHUNK;                            // 0..1023
            int br = cc >> 3, q = cc & 7;                   // br 0..127
            int part = br >> 6, nr = br & 63;
            sa = stB + SWZ128(br * 128 + q * 16);
            g = &g_W1s[((size_t)part * NPAD + n0 + nr) * FIN + k0 + q * 8];
        }
        cp16(sa, g);
    }
    asm volatile("cp.async.commit_group;" ::: "memory");
}

__global__ void __launch_bounds__(256, 2) gemm1_mma_kernel() {
    extern __shared__ char dsmem[];
    const int tid = threadIdx.x;
    const int lane = tid & 31, wid = tid >> 5;
    const int wm = wid & 3;          // warp m index (4)
    const int wn = wid >> 2;         // warp n index (2)
    const int m0 = blockIdx.x * BM;
    const int n0 = blockIdx.y * BN;

    const uint32_t sbase = smem_u32(dsmem);

    float acc[4][4][4];
#pragma unroll
    for (int i = 0; i < 4; i++)
#pragma unroll
        for (int j = 0; j < 4; j++)
#pragma unroll
            for (int c = 0; c < 4; c++) acc[i][j][c] = 0.0f;

    const int ltr = (lane & 7) + ((lane >> 3) & 1) * 8;   // row within 16
    const int lkb = (lane >> 4) * 16;                     // 0 or 16 (k-byte half)

    load_stage(sbase, m0, n0, 0, tid);

    for (int kc = 0; kc < KCH; kc++) {
        if (kc + 1 < KCH) {
            load_stage(sbase + ((kc + 1) & 1) * STAGE_BYTES, m0, n0, (kc + 1) * BK, tid);
            asm volatile("cp.async.wait_group 1;" ::: "memory");
        } else {
            asm volatile("cp.async.wait_group 0;" ::: "memory");
        }
        __syncthreads();

        const uint32_t sA = sbase + (kc & 1) * STAGE_BYTES;
        const uint32_t sB = sA + A_ST_BYTES;

#pragma unroll
        for (int kt = 0; kt < 4; kt++) {
            const int kb = kt * 32 + lkb;
            uint32_t aF[4][4];
#pragma unroll
            for (int im = 0; im < 4; im++) {
                int row = wm * 64 + im * 16 + ltr;
                ldsm4(aF[im], sA + SWZ128(row * 128 + kb));
            }
#pragma unroll
            for (int part = 0; part < NPARTS; part++) {
                uint32_t bF[2][4];
#pragma unroll
                for (int j = 0; j < 2; j++) {
                    int row = part * 64 + wn * 32 + j * 16 + ltr;
                    ldsm4(bF[j], sB + SWZ128(row * 128 + kb));
                }
#pragma unroll
                for (int im = 0; im < 4; im++) {
#pragma unroll
                    for (int j = 0; j < 2; j++) {
                        mma16816(acc[im][j * 2 + 0], aF[im], bF[j][0], bF[j][2]);
                        mma16816(acc[im][j * 2 + 1], aF[im], bF[j][1], bF[j][3]);
                    }
                }
            }
        }
        __syncthreads();
    }

#pragma unroll
    for (int im = 0; im < 4; im++) {
        int m = m0 + wm * 64 + im * 16 + (lane >> 2);
#pragma unroll
        for (int jn = 0; jn < 4; jn++) {
            int n = n0 + wn * 32 + jn * 8 + (lane & 3) * 2;
            if (n < HID) {
                if (m < MROWS)
                    *(float2*)&g_a1[(size_t)m * HID + n] =
                        make_float2(acc[im][jn][0], acc[im][jn][1]);
                if (m + 8 < MROWS)
                    *(float2*)&g_a1[(size_t)(m + 8) * HID + n] =
                        make_float2(acc[im][jn][2], acc[im][jn][3]);
            }
        }
    }
}

// ---------------------------------------------------------------------------
// Kernel 3: PSP + threshold layer 1 -> bf16. Batch-10 load prefetch (MLP=10).
// ---------------------------------------------------------------------------
__global__ void __launch_bounds__(256) psp1_kernel() {
    int tid = blockIdx.x * blockDim.x + threadIdx.x;
    if (tid >= BATCH * HID) return;
    int b = tid / HID;
    int o = tid % HID;
    const float* src = &g_a1[(size_t)b * TBINS * HID + o];
    __nv_bfloat16* dst = &g_s1[(size_t)b * TBINS * HID + o];
    float u = 0.0f;
    for (int tb = 0; tb < TBINS; tb += 10) {
        float x[10];
#pragma unroll
        for (int q = 0; q < 10; q++) x[q] = src[(tb + q) * HID];
#pragma unroll
        for (int q = 0; q < 10; q++) {
            u = fmaf(DECAY, u, x[q]);
            dst[(tb + q) * HID] = __float2bfloat16((u >= THETA) ? 1.0f : 0.0f);
        }
    }
}

// ---------------------------------------------------------------------------
// Kernel 4: GEMM2 (one warp per row, bf16x2 vectorized)
// ---------------------------------------------------------------------------
__global__ void __launch_bounds__(256) gemm2_kernel(const float* __restrict__ W2) {
    __shared__ float2 W2s[NOUT][(HID + 1) / 2 + 1];
    for (int idx = threadIdx.x; idx < NOUT * 206; idx += 256) {
        int j = idx / 206, kp = idx % 206;
        float w0 = (kp * 2 < HID) ? W2[j * HID + kp * 2] : 0.0f;
        float w1 = (kp * 2 + 1 < HID) ? W2[j * HID + kp * 2 + 1] : 0.0f;
        W2s[j][kp] = make_float2(w0, w1);
    }
    __syncthreads();

    int warp = threadIdx.x >> 5;
    int lane = threadIdx.x & 31;
    int m = blockIdx.x * 8 + warp;

    float p[NOUT];
#pragma unroll
    for (int j = 0; j < NOUT; j++) p[j] = 0.0f;

    for (int kp = lane; kp < 205; kp += 32) {
        __nv_bfloat162 sv = *(const __nv_bfloat162*)&g_s1[m * HID + kp * 2];
        float s0 = __bfloat162float(sv.x);
        float s1v = __bfloat162float(sv.y);
#pragma unroll
        for (int j = 0; j < NOUT; j++) {
            float2 w = W2s[j][kp];
            p[j] = fmaf(s0, w.x, fmaf(s1v, w.y, p[j]));
        }
    }

#pragma unroll
    for (int j = 0; j < NOUT; j++)
#pragma unroll
        for (int off = 16; off > 0; off >>= 1)
            p[j] += __shfl_down_sync(0xffffffffu, p[j], off);

    if (lane == 0) {
#pragma unroll
        for (int j = 0; j < NOUT; j++)
            g_a2[m * NOUT + j] = p[j];
    }
}

// ---------------------------------------------------------------------------
// Kernel 5: PSP + threshold layer 2 -> out[b, j, t]. Batch-10 prefetch.
// ---------------------------------------------------------------------------
__global__ void psp2_kernel(float* __restrict__ out) {
    int tid = blockIdx.x * blockDim.x + threadIdx.x;
    if (tid >= BATCH * NOUT) return;
    int b = tid / NOUT;
    int j = tid % NOUT;
    const float* src = &g_a2[(size_t)b * TBINS * NOUT + j];
    float* dst = &out[((size_t)b * NOUT + j) * TBINS];
    float u = 0.0f;
    for (int tb = 0; tb < TBINS; tb += 10) {
        float x[10];
#pragma unroll
        for (int q = 0; q < 10; q++) x[q] = src[(tb + q) * NOUT];
#pragma unroll
        for (int q = 0; q < 10; q++) {
            u = fmaf(DECAY, u, x[q]);
            dst[tb + q] = (u >= THETA) ? 1.0f : 0.0f;
        }
    }
}

// ---------------------------------------------------------------------------
extern "C" void kernel_launch(void* const* d_in, const int* in_sizes, int n_in,
                              void* d_out, int out_size) {
    const float* inp = (const float*)d_in[0];   // [32,3,32,32]
    const float* W1  = (const float*)d_in[1];   // [410,3072]
    const float* W2  = (const float*)d_in[2];   // [10,410]
    float* out = (float*)d_out;                 // [32,10,300]

    cudaFuncSetAttribute(gemm1_mma_kernel,
                         cudaFuncAttributeMaxDynamicSharedMemorySize, DSMEM_BYTES);

    spikegen_kernel<<<(HALFN + 255) / 256, 256>>>(inp, W1);

    dim3 g1((MROWS + BM - 1) / BM, NPAD / BN);   // (38, 7)
    gemm1_mma_kernel<<<g1, 256, DSMEM_BYTES>>>();

    psp1_kernel<<<(BATCH * HID + 255) / 256, 256>>>();
    gemm2_kernel<<<MROWS / 8, 256>>>(W2);
    psp2_kernel<<<2, 160>>>(out);
}

// round 7
// speedup vs baseline: 3.5560x; 1.0136x over previous
#include <cuda_runtime.h>
#include <cuda_fp16.h>
#include <cuda_bf16.h>
#include <cstdint>

// ===========================================================================
// SLAYER SNN forward. GEMM1 on tensor cores via mma.sync.m16n8k16 (fp16),
// 2-part fp16 split of W1 (hi + mid), fp32 accumulation.
// 4-stage cp.async pipeline (BK=32, SW64 swizzle), 1 barrier per chunk.
// ===========================================================================

#define BATCH 32
#define TBINS 300
#define FIN   3072
#define HID   410
#define NOUT  10
#define MROWS (BATCH * TBINS)          // 9600
#define NTOT  (MROWS * FIN)
#define HALFN (NTOT / 2)
#define NPAD  448                      // 7 tiles of 64

#define DECAY 0.90483743f
#define THETA 10.0f

// GEMM1 tiling
#define NPARTS 2
#define BM 256
#define BN 64
#define BK 32
#define KCH (FIN / BK)                 // 96 k-chunks
#define BROWS (NPARTS * BN)            // 128 B rows per stage
#define A_ST_BYTES (BM * 64)           // 16384
#define B_ST_BYTES (BROWS * 64)        // 8192
#define STAGE_BYTES (A_ST_BYTES + B_ST_BYTES)   // 24576
#define NSTAGES 4
#define DSMEM_BYTES (NSTAGES * STAGE_BYTES)     // 98304
#define NCHUNK (STAGE_BYTES / 16)      // 1536 16B chunks / stage
#define ACHUNK (A_ST_BYTES / 16)       // 1024

#define SWZ64(off) ((off) ^ (((off) >> 3) & 0x30))

// Scratch
__device__ __align__(16) __half        g_spikes[NTOT];        // [9600,3072] 0/1
__device__ __align__(16) __half        g_W1s[NPARTS * NPAD * FIN]; // zero-padded rows
__device__ __align__(16) float         g_a1[MROWS * HID];
__device__ __align__(16) __nv_bfloat16 g_s1[MROWS * HID];
__device__ __align__(16) float         g_a2[MROWS * NOUT];

// ---------------------------------------------------------------------------
__device__ __forceinline__ uint32_t smem_u32(const void* p) {
    uint32_t a;
    asm("{ .reg .u64 t; cvta.to.shared.u64 t, %1; cvt.u32.u64 %0, t; }" : "=r"(a) : "l"(p));
    return a;
}
__device__ __forceinline__ void cp16(uint32_t sa, const void* g) {
    asm volatile("cp.async.cg.shared.global [%0], [%1], 16;" :: "r"(sa), "l"(g));
}
__device__ __forceinline__ void ldsm4(uint32_t* r, uint32_t addr) {
    asm volatile("ldmatrix.sync.aligned.m8n8.x4.shared.b16 {%0,%1,%2,%3}, [%4];"
                 : "=r"(r[0]), "=r"(r[1]), "=r"(r[2]), "=r"(r[3]) : "r"(addr));
}
__device__ __forceinline__ void mma16816(float* c, const uint32_t* a,
                                         uint32_t b0, uint32_t b1) {
    asm volatile(
        "mma.sync.aligned.m16n8k16.row.col.f32.f16.f16.f32 "
        "{%0,%1,%2,%3}, {%4,%5,%6,%7}, {%8,%9}, {%0,%1,%2,%3};"
        : "+f"(c[0]), "+f"(c[1]), "+f"(c[2]), "+f"(c[3])
        : "r"(a[0]), "r"(a[1]), "r"(a[2]), "r"(a[3]), "r"(b0), "r"(b1));
}

// ---------------------------------------------------------------------------
// Kernel 1: threefry-2x32 spike generation -> fp16 (bit-exact vs jax).
// Also performs the 2-part fp16 split of W1 on its first HID*FIN threads.
// ---------------------------------------------------------------------------
__device__ __forceinline__ uint32_t rotl32(uint32_t x, int r) {
    return (x << r) | (x >> (32 - r));
}

__global__ void __launch_bounds__(256) spikegen_kernel(const float* __restrict__ inp,
                                                       const float* __restrict__ W1) {
    uint32_t i = blockIdx.x * 256u + threadIdx.x;
    if (i >= HALFN) return;

    // --- W1 split (piggybacked on first 1.26M threads) ---
    if (i < HID * FIN) {
        float w = W1[i];
        __half h = __float2half_rn(w);
        float r1 = w - __half2float(h);
        __half m = __float2half_rn(r1);
        int n = i / FIN, k = i % FIN;
        g_W1s[(0 * NPAD + n) * FIN + k] = h;
        g_W1s[(1 * NPAD + n) * FIN + k] = m;
    }

    const uint32_t k0 = 0u, k1 = 42u, k2 = 0x1BD11BDAu ^ k0 ^ k1;
    uint32_t x0 = i + k0;
    uint32_t x1 = (i + HALFN) + k1;

#define TF_RND(r) { x0 += x1; x1 = rotl32(x1, (r)) ^ x0; }
    TF_RND(13) TF_RND(15) TF_RND(26) TF_RND(6)
    x0 += k1; x1 += k2 + 1u;
    TF_RND(17) TF_RND(29) TF_RND(16) TF_RND(24)
    x0 += k2; x1 += k0 + 2u;
    TF_RND(13) TF_RND(15) TF_RND(26) TF_RND(6)
    x0 += k0; x1 += k1 + 3u;
    TF_RND(17) TF_RND(29) TF_RND(16) TF_RND(24)
    x0 += k1; x1 += k2 + 4u;
    TF_RND(13) TF_RND(15) TF_RND(26) TF_RND(6)
    x0 += k2; x1 += k0 + 5u;
#undef TF_RND

    float u0 = __uint_as_float((x0 >> 9) | 0x3F800000u) - 1.0f;
    float u1 = __uint_as_float((x1 >> 9) | 0x3F800000u) - 1.0f;

    uint32_t ia = i, ib = i + HALFN;
    uint32_t ba = ia / (TBINS * FIN), fa = ia % FIN;
    uint32_t bb = ib / (TBINS * FIN), fb = ib % FIN;
    float pa = __ldg(&inp[ba * FIN + fa]);
    float pb = __ldg(&inp[bb * FIN + fb]);

    g_spikes[ia] = __ushort_as_half((u0 < pa) ? (unsigned short)0x3C00 : (unsigned short)0);
    g_spikes[ib] = __ushort_as_half((u1 < pb) ? (unsigned short)0x3C00 : (unsigned short)0);
}

// ---------------------------------------------------------------------------
// Kernel 2: GEMM1, mma.sync fp16, 4-stage cp.async pipeline, SW64 smem.
// a1[m,n] = sum_k spikes[m,k] * (W1hi + W1mid)[n,k]
// ---------------------------------------------------------------------------
__device__ __forceinline__ void load_stage(uint32_t sbase, int m0, int n0, int k0,
                                           int tid) {
    uint32_t stB = sbase + A_ST_BYTES;
#pragma unroll
    for (int c = tid; c < NCHUNK; c += 256) {
        uint32_t sa;
        const __half* g;
        if (c < ACHUNK) {                               // A: 1024 chunks
            int row = c >> 2, q = c & 3;
            int m = m0 + row;
            if (m >= MROWS) m = MROWS - 1;              // clamp (discarded later)
            sa = sbase + SWZ64(row * 64 + q * 16);
            g = &g_spikes[(size_t)m * FIN + k0 + q * 8];
        } else {                                        // B: 512 chunks
            int cc = c - ACHUNK;
            int br = cc >> 2, q = cc & 3;               // br 0..127
            int part = br >> 6, nr = br & 63;
            sa = stB + SWZ64(br * 64 + q * 16);
            g = &g_W1s[((size_t)part * NPAD + n0 + nr) * FIN + k0 + q * 8];
        }
        cp16(sa, g);
    }
    asm volatile("cp.async.commit_group;" ::: "memory");
}

__global__ void __launch_bounds__(256, 2) gemm1_mma_kernel() {
    extern __shared__ char dsmem[];
    const int tid = threadIdx.x;
    const int lane = tid & 31, wid = tid >> 5;
    const int wm = wid & 3;          // warp m index (4)
    const int wn = wid >> 2;         // warp n index (2)
    const int m0 = blockIdx.x * BM;
    const int n0 = blockIdx.y * BN;

    const uint32_t sbase = smem_u32(dsmem);

    float acc[4][4][4];
#pragma unroll
    for (int i = 0; i < 4; i++)
#pragma unroll
        for (int j = 0; j < 4; j++)
#pragma unroll
            for (int c = 0; c < 4; c++) acc[i][j][c] = 0.0f;

    const int ltr = (lane & 7) + ((lane >> 3) & 1) * 8;   // row within 16
    const int lkb = (lane >> 4) * 16;                     // 0 or 16 (k-byte half)

    // prologue: 3 stages in flight
    load_stage(sbase + 0 * STAGE_BYTES, m0, n0, 0 * BK, tid);
    load_stage(sbase + 1 * STAGE_BYTES, m0, n0, 1 * BK, tid);
    load_stage(sbase + 2 * STAGE_BYTES, m0, n0, 2 * BK, tid);

    for (int kc = 0; kc < KCH; kc++) {
        // ensure stage kc's group is complete (2/1/0 newer groups pending)
        const int rem = KCH - 1 - kc;
        if (rem >= 2)      asm volatile("cp.async.wait_group 2;" ::: "memory");
        else if (rem == 1) asm volatile("cp.async.wait_group 1;" ::: "memory");
        else               asm volatile("cp.async.wait_group 0;" ::: "memory");
        __syncthreads();

        // prefetch stage kc+3 into the buffer freed by stage kc-1
        if (kc + 3 < KCH)
            load_stage(sbase + ((kc + 3) & 3) * STAGE_BYTES, m0, n0, (kc + 3) * BK, tid);

        const uint32_t sA = sbase + (kc & 3) * STAGE_BYTES;
        const uint32_t sB = sA + A_ST_BYTES;

#pragma unroll
        for (int kt = 0; kt < 2; kt++) {
            const int kb = kt * 32 + lkb;
            uint32_t aF[4][4];
#pragma unroll
            for (int im = 0; im < 4; im++) {
                int row = wm * 64 + im * 16 + ltr;
                ldsm4(aF[im], sA + SWZ64(row * 64 + kb));
            }
#pragma unroll
            for (int part = 0; part < NPARTS; part++) {
                uint32_t bF[2][4];
#pragma unroll
                for (int j = 0; j < 2; j++) {
                    int row = part * 64 + wn * 32 + j * 16 + ltr;
                    ldsm4(bF[j], sB + SWZ64(row * 64 + kb));
                }
#pragma unroll
                for (int im = 0; im < 4; im++) {
#pragma unroll
                    for (int j = 0; j < 2; j++) {
                        mma16816(acc[im][j * 2 + 0], aF[im], bF[j][0], bF[j][2]);
                        mma16816(acc[im][j * 2 + 1], aF[im], bF[j][1], bF[j][3]);
                    }
                }
            }
        }
    }

#pragma unroll
    for (int im = 0; im < 4; im++) {
        int m = m0 + wm * 64 + im * 16 + (lane >> 2);
#pragma unroll
        for (int jn = 0; jn < 4; jn++) {
            int n = n0 + wn * 32 + jn * 8 + (lane & 3) * 2;
            if (n < HID) {
                if (m < MROWS)
                    *(float2*)&g_a1[(size_t)m * HID + n] =
                        make_float2(acc[im][jn][0], acc[im][jn][1]);
                if (m + 8 < MROWS)
                    *(float2*)&g_a1[(size_t)(m + 8) * HID + n] =
                        make_float2(acc[im][jn][2], acc[im][jn][3]);
            }
        }
    }
}

// ---------------------------------------------------------------------------
// Kernel 3: PSP + threshold layer 1 -> bf16. Batch-10 load prefetch (MLP=10).
// ---------------------------------------------------------------------------
__global__ void __launch_bounds__(256) psp1_kernel() {
    int tid = blockIdx.x * blockDim.x + threadIdx.x;
    if (tid >= BATCH * HID) return;
    int b = tid / HID;
    int o = tid % HID;
    const float* src = &g_a1[(size_t)b * TBINS * HID + o];
    __nv_bfloat16* dst = &g_s1[(size_t)b * TBINS * HID + o];
    float u = 0.0f;
    for (int tb = 0; tb < TBINS; tb += 10) {
        float x[10];
#pragma unroll
        for (int q = 0; q < 10; q++) x[q] = src[(tb + q) * HID];
#pragma unroll
        for (int q = 0; q < 10; q++) {
            u = fmaf(DECAY, u, x[q]);
            dst[(tb + q) * HID] = __float2bfloat16((u >= THETA) ? 1.0f : 0.0f);
        }
    }
}

// ---------------------------------------------------------------------------
// Kernel 4: GEMM2 (one warp per row, bf16x2 vectorized)
// ---------------------------------------------------------------------------
__global__ void __launch_bounds__(256) gemm2_kernel(const float* __restrict__ W2) {
    __shared__ float2 W2s[NOUT][(HID + 1) / 2 + 1];
    for (int idx = threadIdx.x; idx < NOUT * 206; idx += 256) {
        int j = idx / 206, kp = idx % 206;
        float w0 = (kp * 2 < HID) ? W2[j * HID + kp * 2] : 0.0f;
        float w1 = (kp * 2 + 1 < HID) ? W2[j * HID + kp * 2 + 1] : 0.0f;
        W2s[j][kp] = make_float2(w0, w1);
    }
    __syncthreads();

    int warp = threadIdx.x >> 5;
    int lane = threadIdx.x & 31;
    int m = blockIdx.x * 8 + warp;

    float p[NOUT];
#pragma unroll
    for (int j = 0; j < NOUT; j++) p[j] = 0.0f;

    for (int kp = lane; kp < 205; kp += 32) {
        __nv_bfloat162 sv = *(const __nv_bfloat162*)&g_s1[m * HID + kp * 2];
        float s0 = __bfloat162float(sv.x);
        float s1v = __bfloat162float(sv.y);
#pragma unroll
        for (int j = 0; j < NOUT; j++) {
            float2 w = W2s[j][kp];
            p[j] = fmaf(s0, w.x, fmaf(s1v, w.y, p[j]));
        }
    }

#pragma unroll
    for (int j = 0; j < NOUT; j++)
#pragma unroll
        for (int off = 16; off > 0; off >>= 1)
            p[j] += __shfl_down_sync(0xffffffffu, p[j], off);

    if (lane == 0) {
#pragma unroll
        for (int j = 0; j < NOUT; j++)
            g_a2[m * NOUT + j] = p[j];
    }
}

// ---------------------------------------------------------------------------
// Kernel 5: PSP + threshold layer 2 -> out[b, j, t]. Batch-10 prefetch.
// ---------------------------------------------------------------------------
__global__ void psp2_kernel(float* __restrict__ out) {
    int tid = blockIdx.x * blockDim.x + threadIdx.x;
    if (tid >= BATCH * NOUT) return;
    int b = tid / NOUT;
    int j = tid % NOUT;
    const float* src = &g_a2[(size_t)b * TBINS * NOUT + j];
    float* dst = &out[((size_t)b * NOUT + j) * TBINS];
    float u = 0.0f;
    for (int tb = 0; tb < TBINS; tb += 10) {
        float x[10];
#pragma unroll
        for (int q = 0; q < 10; q++) x[q] = src[(tb + q) * NOUT];
#pragma unroll
        for (int q = 0; q < 10; q++) {
            u = fmaf(DECAY, u, x[q]);
            dst[tb + q] = (u >= THETA) ? 1.0f : 0.0f;
        }
    }
}

// ---------------------------------------------------------------------------
extern "C" void kernel_launch(void* const* d_in, const int* in_sizes, int n_in,
                              void* d_out, int out_size) {
    const float* inp = (const float*)d_in[0];   // [32,3,32,32]
    const float* W1  = (const float*)d_in[1];   // [410,3072]
    const float* W2  = (const float*)d_in[2];   // [10,410]
    float* out = (float*)d_out;                 // [32,10,300]

    cudaFuncSetAttribute(gemm1_mma_kernel,
                         cudaFuncAttributeMaxDynamicSharedMemorySize, DSMEM_BYTES);

    spikegen_kernel<<<(HALFN + 255) / 256, 256>>>(inp, W1);

    dim3 g1((MROWS + BM - 1) / BM, NPAD / BN);   // (38, 7)
    gemm1_mma_kernel<<<g1, 256, DSMEM_BYTES>>>();

    psp1_kernel<<<(BATCH * HID + 255) / 256, 256>>>();
    gemm2_kernel<<<MROWS / 8, 256>>>(W2);
    psp2_kernel<<<2, 160>>>(out);
}